// round 10
// baseline (speedup 1.0000x reference)
#include <cuda_runtime.h>
#include <cuda_bf16.h>
#include <math.h>

// Fused quantized LeNet, round 10: FFMA2 with zero-ALU x operands.
// x (input & pool1) stored DUPLICATED in smem ({x,x} pairs) so broadcast
// operands load directly into aligned register pairs via LDS.128.
// Accumulators pack {top conv row, bot conv row}; weight pairs {w[r],w[r-1]}
// packed on the fly (5/row). Same accumulation order as R5/R9 => same rel_err.

#define B        1024
#define NTHR     160

typedef unsigned long long u64;

__device__ __forceinline__ float q8(float x) {
    return rintf(x * 256.0f) * 0.00390625f;   // round-half-even, scale 2^-8
}
__device__ __forceinline__ float clipf(float x) {
    return fminf(fmaxf(x, -256.0f), 255.0f);
}
__device__ __forceinline__ u64 pk(float lo, float hi) {
    u64 r; asm("mov.b64 %0,{%1,%2};" : "=l"(r) : "f"(lo), "f"(hi)); return r;
}
__device__ __forceinline__ void fma2(u64& a, u64 b, u64 c) {
    asm("fma.rn.f32x2 %0,%1,%2,%0;" : "+l"(a) : "l"(b), "l"(c));
}
__device__ __forceinline__ void unpk(u64 p, float& lo, float& hi) {
    asm("mov.b64 {%0,%1},%2;" : "=f"(lo), "=f"(hi) : "l"(p));
}

// ---- quantized weight scratch ---------------------------------------------
__device__ __align__(16) float g_qc1wp[280];   // 10 x 28 (25 taps + pad), q8
__device__ float g_qc1b[10];
__device__ __align__(16) float g_qc2wp[5600];  // 20 x 10 x 28, q8
__device__ float g_qc2b[20];
__device__ __align__(16) float g_qf1wT[16640]; // 320 x 52 transposed, clip(q8)
__device__ float g_qf1b[50];
__device__ __align__(16) float g_qf2w[500];    // 10 x 50, clip(q8)
__device__ float g_qf2b[10];

// ---------------------------------------------------------------------------
__global__ void k_quant_weights(const float* __restrict__ c1w, const float* __restrict__ c1b,
                                const float* __restrict__ c2w, const float* __restrict__ c2b,
                                const float* __restrict__ f1w, const float* __restrict__ f1b,
                                const float* __restrict__ f2w, const float* __restrict__ f2b)
{
    int i = blockIdx.x * blockDim.x + threadIdx.x;
    if (i < 280) {
        int j = i / 28, t = i % 28;
        g_qc1wp[i] = (t < 25) ? q8(c1w[j * 25 + t]) : 0.f;
    } else if (i < 290) {
        g_qc1b[i - 280] = q8(c1b[i - 280]);
    } else if (i < 5890) {
        int r = i - 290;
        int jc = r / 28, t = r % 28;
        g_qc2wp[r] = (t < 25) ? q8(c2w[jc * 25 + t]) : 0.f;
    } else if (i < 5910) {
        g_qc2b[i - 5890] = q8(c2b[i - 5890]);
    } else if (i < 22550) {
        int r = i - 5910;
        int k = r / 52, l = r % 52;
        g_qf1wT[r] = (l < 50) ? clipf(q8(f1w[l * 320 + k])) : 0.f;
    } else if (i < 22600) {
        g_qf1b[i - 22550] = clipf(q8(f1b[i - 22550]));
    } else if (i < 23100) {
        g_qf2w[i - 22600] = clipf(q8(f2w[i - 22600]));
    } else if (i < 23110) {
        g_qf2b[i - 23100] = clipf(q8(f2b[i - 23100]));
    }
}

// ---- smem layout (floats) --------------------------------------------------
// XQD: 28x28 input, DUPLICATED pairs -> rows of 56 floats. 1568 total.
// P1D: pool1 10ch x 12 rows, DUPLICATED -> rows of 24 floats. 2880 total.
#define S_XQD  0        // 1568   (aliased by fc scratch after conv1)
#define S_P1D  1568     // 2880
#define S_P2   4448     // 320 (scalar, for fc1)
#define S_TOT  4768     // 19072 bytes
// fc scratch aliases S_XQD:
#define S_PART 0        // [2 slices][52]
#define S_H1   104      // [52]
#define S_Z    160      // [12]

// Load 25 padded taps (7 float4) from gmem into registers.
__device__ __forceinline__ void load_w25(const float* gw, float* wr)
{
    const float4* w4 = (const float4*)gw;
    float wf[28];
    #pragma unroll
    for (int q = 0; q < 7; q++) {
        float4 t = __ldg(w4 + q);
        wf[q*4+0]=t.x; wf[q*4+1]=t.y; wf[q*4+2]=t.z; wf[q*4+3]=t.w;
    }
    #pragma unroll
    for (int q = 0; q < 25; q++) wr[q] = wf[q];
}

// One duplicated input row (8 original values = 16 floats = 4x LDS.128, each
// yielding two aligned {x,x} u64 pairs) accumulated into 4 packed {top,bot}
// column accumulators. r in 0..5 relative to pooled pair's top conv row.
__device__ __forceinline__ void pair_row_dup(const float* rp, int r,
                                             const float* wr, u64* AC)
{
    const ulonglong2* vp = (const ulonglong2*)rp;
    ulonglong2 L0 = vp[0], L1 = vp[1], L2 = vp[2], L3 = vp[3];
    u64 rb[8] = {L0.x, L0.y, L1.x, L1.y, L2.x, L2.y, L3.x, L3.y};
    #pragma unroll
    for (int v = 0; v < 5; v++) {
        const float wt = (r < 5)  ? wr[r * 5 + v]       : 0.f;
        const float wb = (r >= 1) ? wr[(r - 1) * 5 + v] : 0.f;
        const u64 wp = pk(wt, wb);
        fma2(AC[0], wp, rb[v + 0]);
        fma2(AC[1], wp, rb[v + 1]);
        fma2(AC[2], wp, rb[v + 2]);
        fma2(AC[3], wp, rb[v + 3]);
    }
}

// ---------------------------------------------------------------------------
__global__ __launch_bounds__(NTHR) void k_fused(const float* __restrict__ x,
                                                float* __restrict__ out)
{
    __shared__ __align__(16) float sm[S_TOT];
    const int tid = threadIdx.x;
    const int blk = blockIdx.x;

    // ---- stage 0: quantized input to smem, duplicated ---------------------
    {
        const float* xin = x + (size_t)blk * 784;
        for (int i = tid; i < 784; i += NTHR) {
            const float v = q8(xin[i]);
            *(float2*)(sm + S_XQD + 2 * i) = make_float2(v, v);
        }
    }
    __syncthreads();

    // ---- stage 1: conv1 + pool + relu -> P1D (duplicated) -----------------
    // thread = (j in 10, tt in 16); adjacent-pw pairs, c0 4-aligned.
    {
        const int j  = tid / 16;
        const int tt = tid % 16;
        float wr[25];
        load_w25(g_qc1wp + j * 28, wr);
        const float bj = __ldg(&g_qc1b[j]);
        float* outp = sm + S_P1D + j * 288;

        #pragma unroll
        for (int qq = 0; qq < 5; qq++) {
            const int q = tt + 16 * qq;          // 0..79, guard <72
            if (q < 72) {
                const int ph = q / 6, pwp = q % 6;
                const int r0 = 2 * ph;

                u64 AC[4];
                #pragma unroll
                for (int z = 0; z < 4; z++) AC[z] = pk(0.f, 0.f);

                #pragma unroll
                for (int r = 0; r < 6; r++)
                    pair_row_dup(sm + S_XQD + (r0 + r) * 56 + 8 * pwp, r, wr, AC);

                float t0, b0, t1, b1, t2, b2, t3, b3;
                unpk(AC[0], t0, b0); unpk(AC[1], t1, b1);
                unpk(AC[2], t2, b2); unpk(AC[3], t3, b3);
                float m0 = fmaxf(fmaxf(t0, t1), fmaxf(b0, b1)) + bj;
                float m1 = fmaxf(fmaxf(t2, t3), fmaxf(b2, b3)) + bj;
                m0 = fmaxf(m0, 0.f);
                m1 = fmaxf(m1, 0.f);
                // duplicated write: {m0,m0,m1,m1}, 16B-aligned
                *(float4*)(outp + ph * 24 + 4 * pwp) = make_float4(m0, m0, m1, m1);
            }
        }
    }
    __syncthreads();

    // ---- stage 2: conv2 + pool + relu + q8 -> s_p2 (scalar) ---------------
    // thread = (oc in 20, ph in 4, pwh in 2); 2 pooled outputs each.
    {
        const int oc  = tid >> 3;
        const int pp  = tid & 7;
        const int ph  = pp >> 1;
        const int pwh = pp & 1;
        const int r0  = 2 * ph;

        u64 AC[4];
        #pragma unroll
        for (int z = 0; z < 4; z++) AC[z] = pk(0.f, 0.f);

        #pragma unroll 1
        for (int c = 0; c < 10; c++) {
            float wr[25];
            load_w25(g_qc2wp + (oc * 10 + c) * 28, wr);
            const float* xc = sm + S_P1D + c * 288 + 8 * pwh;
            #pragma unroll
            for (int r = 0; r < 6; r++)
                pair_row_dup(xc + (r0 + r) * 24, r, wr, AC);
        }
        const float bj = __ldg(&g_qc2b[oc]);
        float t0, b0, t1, b1, t2, b2, t3, b3;
        unpk(AC[0], t0, b0); unpk(AC[1], t1, b1);
        unpk(AC[2], t2, b2); unpk(AC[3], t3, b3);
        float m0 = fmaxf(fmaxf(t0, t1), fmaxf(b0, b1)) + bj;
        float m1 = fmaxf(fmaxf(t2, t3), fmaxf(b2, b3)) + bj;
        sm[S_P2 + oc * 16 + ph * 4 + pwh * 2]     = q8(fmaxf(m0, 0.f));
        sm[S_P2 + oc * 16 + ph * 4 + pwh * 2 + 1] = q8(fmaxf(m1, 0.f));
    }
    __syncthreads();

    // ---- stage 3: fc1 partials (k-split x2) -------------------------------
    if (tid < 100) {
        const int l = tid % 50;
        const int s = tid / 50;
        const float* wT = g_qf1wT + l;
        const float* p2 = sm + S_P2;
        float acc = 0.f;
        const int k0 = 160 * s;
        #pragma unroll 4
        for (int k = k0; k < k0 + 160; k++)
            acc = fmaf(__ldg(wT + k * 52), p2[k], acc);
        sm[S_PART + s * 52 + l] = acc;
    }
    __syncthreads();

    // ---- stage 4: fc1 reduce + clip/relu/q8 -------------------------------
    if (tid < 50) {
        float acc = sm[S_PART + tid] + sm[S_PART + 52 + tid];
        float h = clipf(acc + __ldg(&g_qf1b[tid]));
        h = fmaxf(h, 0.f);
        sm[S_H1 + tid] = q8(h);
    }
    __syncthreads();

    // ---- stage 5: fc2 + clip ---------------------------------------------
    if (tid < 10) {
        const float* w = g_qf2w + tid * 50;
        float acc = 0.f;
        #pragma unroll
        for (int k = 0; k < 50; k++) acc = fmaf(__ldg(w + k), sm[S_H1 + k], acc);
        sm[S_Z + tid] = clipf(acc + __ldg(&g_qf2b[tid]));
    }
    __syncthreads();

    // ---- stage 6: log_softmax --------------------------------------------
    if (tid < 10) {
        const float* z = sm + S_Z;
        float m = -1e30f;
        #pragma unroll
        for (int k = 0; k < 10; k++) m = fmaxf(m, z[k]);
        float s = 0.f;
        #pragma unroll
        for (int k = 0; k < 10; k++) s += expf(z[k] - m);
        out[blk * 10 + tid] = z[tid] - m - logf(s);
    }
}

// ---------------------------------------------------------------------------
extern "C" void kernel_launch(void* const* d_in, const int* in_sizes, int n_in,
                              void* d_out, int out_size)
{
    const float* x   = (const float*)d_in[0];
    const float* c1w = (const float*)d_in[1];
    const float* c1b = (const float*)d_in[2];
    const float* c2w = (const float*)d_in[3];
    const float* c2b = (const float*)d_in[4];
    const float* f1w = (const float*)d_in[5];
    const float* f1b = (const float*)d_in[6];
    const float* f2w = (const float*)d_in[7];
    const float* f2b = (const float*)d_in[8];
    float* out = (float*)d_out;

    k_quant_weights<<<(23110 + 255) / 256, 256>>>(c1w, c1b, c2w, c2b, f1w, f1b, f2w, f2b);
    k_fused<<<B, NTHR>>>(x, out);
}

// round 11
// speedup vs baseline: 1.2846x; 1.2846x over previous
#include <cuda_runtime.h>
#include <cuda_bf16.h>
#include <math.h>

// Fused quantized LeNet, round 11: R5 chassis (best: 36.9us) with conv2
// replaced by a BALANCED quad tiling: thread = (oc x quad x chalf) = 20x4x2
// = exactly 160 threads, no divergent guard (R7/R8's hidden flaw). 16 accs
// over an 8x8 patch -> 25 FMA per LDS.128; chalf halves weight LDGs; one
// shfl_xor(1) merges channel halves. conv1/fc stages identical to R5.
// Conv per-product clip never fires (|w*x| <= ~13 << 255): convs pure FMA.

#define B        1024
#define NTHR     160

__device__ __forceinline__ float q8(float x) {
    return rintf(x * 256.0f) * 0.00390625f;   // round-half-even, scale 2^-8
}
__device__ __forceinline__ float clipf(float x) {
    return fminf(fmaxf(x, -256.0f), 255.0f);
}

// ---- quantized weight scratch ---------------------------------------------
__device__ __align__(16) float g_qc1wp[280];   // 10 x 28 (25 taps + pad), q8
__device__ float g_qc1b[10];
__device__ __align__(16) float g_qc2wp[5600];  // 20 x 10 x 28, q8
__device__ float g_qc2b[20];
__device__ __align__(16) float g_qf1wT[16640]; // 320 x 52 transposed, clip(q8)
__device__ float g_qf1b[50];
__device__ __align__(16) float g_qf2w[500];    // 10 x 50, clip(q8)
__device__ float g_qf2b[10];

// ---------------------------------------------------------------------------
__global__ void k_quant_weights(const float* __restrict__ c1w, const float* __restrict__ c1b,
                                const float* __restrict__ c2w, const float* __restrict__ c2b,
                                const float* __restrict__ f1w, const float* __restrict__ f1b,
                                const float* __restrict__ f2w, const float* __restrict__ f2b)
{
    int i = blockIdx.x * blockDim.x + threadIdx.x;
    if (i < 280) {
        int j = i / 28, t = i % 28;
        g_qc1wp[i] = (t < 25) ? q8(c1w[j * 25 + t]) : 0.f;
    } else if (i < 290) {
        g_qc1b[i - 280] = q8(c1b[i - 280]);
    } else if (i < 5890) {
        int r = i - 290;
        int jc = r / 28, t = r % 28;
        g_qc2wp[r] = (t < 25) ? q8(c2w[jc * 25 + t]) : 0.f;
    } else if (i < 5910) {
        g_qc2b[i - 5890] = q8(c2b[i - 5890]);
    } else if (i < 22550) {
        int r = i - 5910;
        int k = r / 52, l = r % 52;
        g_qf1wT[r] = (l < 50) ? clipf(q8(f1w[l * 320 + k])) : 0.f;
    } else if (i < 22600) {
        g_qf1b[i - 22550] = clipf(q8(f1b[i - 22550]));
    } else if (i < 23100) {
        g_qf2w[i - 22600] = clipf(q8(f2w[i - 22600]));
    } else if (i < 23110) {
        g_qf2b[i - 23100] = clipf(q8(f2b[i - 23100]));
    }
}

// ---- smem layout (floats) --------------------------------------------------
#define S_XQ   0        // 784            (aliased by fc scratch after conv1)
#define S_P1   784      // 10 ch x 12 rows x 20 = 2400 (rows padded to 20)
#define S_P2   3184     // 320
#define S_TOT  3504     // 14016 bytes
// fc scratch aliases S_XQ:
#define S_PART 0        // [2 slices][52]
#define S_H1   104      // [52]
#define S_Z    160      // [12]

// Load 25 padded taps (7 float4) from gmem into registers.
__device__ __forceinline__ void load_w25(const float* gw, float* wr)
{
    const float4* w4 = (const float4*)gw;
    float wf[28];
    #pragma unroll
    for (int q = 0; q < 7; q++) {
        float4 t = __ldg(w4 + q);
        wf[q*4+0]=t.x; wf[q*4+1]=t.y; wf[q*4+2]=t.z; wf[q*4+3]=t.w;
    }
    #pragma unroll
    for (int q = 0; q < 25; q++) wr[q] = wf[q];
}

// Accumulate one 8-float input row into the 4x4 conv-output accumulator tile.
// r = input row index relative to quad top (0..7). A[R*4+C], R,C in 0..3.
__device__ __forceinline__ void quad_row(const float* rp, int r,
                                         const float* wr, float* A)
{
    float4 Av = *(const float4*)rp;
    float4 Cv = *(const float4*)(rp + 4);
    float row[8] = {Av.x, Av.y, Av.z, Av.w, Cv.x, Cv.y, Cv.z, Cv.w};
    #pragma unroll
    for (int R = 0; R < 4; R++) {
        const int u = r - R;
        if (u >= 0 && u <= 4) {
            #pragma unroll
            for (int v = 0; v < 5; v++) {
                const float wv = wr[u * 5 + v];
                A[R * 4 + 0] = fmaf(wv, row[v + 0], A[R * 4 + 0]);
                A[R * 4 + 1] = fmaf(wv, row[v + 1], A[R * 4 + 1]);
                A[R * 4 + 2] = fmaf(wv, row[v + 2], A[R * 4 + 2]);
                A[R * 4 + 3] = fmaf(wv, row[v + 3], A[R * 4 + 3]);
            }
        }
    }
}

// ---------------------------------------------------------------------------
__global__ __launch_bounds__(NTHR) void k_fused(const float* __restrict__ x,
                                                float* __restrict__ out)
{
    __shared__ __align__(16) float sm[S_TOT];
    const int tid = threadIdx.x;
    const int blk = blockIdx.x;

    // ---- stage 0: quantized input to smem ---------------------------------
    {
        const float* xin = x + (size_t)blk * 784;
        for (int i = tid; i < 784; i += NTHR) sm[S_XQ + i] = q8(xin[i]);
    }
    __syncthreads();

    // ---- stage 1: conv1 + pool + relu -> s_p1 (R5-proven mapping) ---------
    // thread = (j in 10, tt in 16); adjacent-pw pairs, c0 4-aligned.
    {
        const int j  = tid / 16;
        const int tt = tid % 16;
        float wr[25];
        load_w25(g_qc1wp + j * 28, wr);
        const float bj = __ldg(&g_qc1b[j]);
        const float* xb = sm + S_XQ;
        float* outp = sm + S_P1 + j * 240;

        #pragma unroll
        for (int qq = 0; qq < 5; qq++) {
            const int q = tt + 16 * qq;          // 0..79, guard <72
            if (q < 72) {
                const int ph = q / 6, pwp = q % 6;
                const int r0 = 2 * ph, cb = 4 * pwp;

                float a[8];
                #pragma unroll
                for (int z = 0; z < 8; z++) a[z] = 0.f;

                #pragma unroll
                for (int r = 0; r < 6; r++) {
                    const float* rp = xb + (r0 + r) * 28 + cb;
                    float4 A = *(const float4*)rp;
                    float4 C = *(const float4*)(rp + 4);
                    float row[8] = {A.x, A.y, A.z, A.w, C.x, C.y, C.z, C.w};
                    if (r < 5) {
                        #pragma unroll
                        for (int v = 0; v < 5; v++) {
                            const float wv = wr[r * 5 + v];
                            a[0] = fmaf(wv, row[v],     a[0]);
                            a[1] = fmaf(wv, row[v + 1], a[1]);
                            a[4] = fmaf(wv, row[v + 2], a[4]);
                            a[5] = fmaf(wv, row[v + 3], a[5]);
                        }
                    }
                    if (r >= 1) {
                        #pragma unroll
                        for (int v = 0; v < 5; v++) {
                            const float wv = wr[(r - 1) * 5 + v];
                            a[2] = fmaf(wv, row[v],     a[2]);
                            a[3] = fmaf(wv, row[v + 1], a[3]);
                            a[6] = fmaf(wv, row[v + 2], a[6]);
                            a[7] = fmaf(wv, row[v + 3], a[7]);
                        }
                    }
                }
                float m0 = fmaxf(fmaxf(a[0], a[1]), fmaxf(a[2], a[3])) + bj;
                float m1 = fmaxf(fmaxf(a[4], a[5]), fmaxf(a[6], a[7])) + bj;
                outp[ph * 20 + 2 * pwp]     = fmaxf(m0, 0.f);
                outp[ph * 20 + 2 * pwp + 1] = fmaxf(m1, 0.f);
            }
        }
    }
    __syncthreads();

    // ---- stage 2: conv2 + pool + relu + q8 (BALANCED quad + chalf) --------
    // thread = (oc in 20, quad in 4, chalf in 2) = exactly 160, no guards.
    {
        const int chalf = tid & 1;
        const int quad  = (tid >> 1) & 3;
        const int oc    = tid >> 3;
        const int qph = quad >> 1, qpw = quad & 1;
        const int rbase = 4 * qph;
        const int cbase = 4 * qpw;

        float A[16];
        #pragma unroll
        for (int z = 0; z < 16; z++) A[z] = 0.f;

        #pragma unroll 1
        for (int cc = 0; cc < 5; cc++) {
            const int c = chalf * 5 + cc;
            float wr[25];
            load_w25(g_qc2wp + (oc * 10 + c) * 28, wr);
            const float* xc = sm + S_P1 + c * 240 + cbase;
            #pragma unroll
            for (int r = 0; r < 8; r++)
                quad_row(xc + (rbase + r) * 20, r, wr, A);
        }
        // merge channel halves: partner lane differs only in chalf (lane^1)
        #pragma unroll
        for (int z = 0; z < 16; z++)
            A[z] += __shfl_xor_sync(0xFFFFFFFFu, A[z], 1);

        if (chalf == 0) {
            const float bj = __ldg(&g_qc2b[oc]);
            #pragma unroll
            for (int dph = 0; dph < 2; dph++)
                #pragma unroll
                for (int dpw = 0; dpw < 2; dpw++) {
                    float m = fmaxf(fmaxf(A[(2*dph)*4 + 2*dpw],   A[(2*dph)*4 + 2*dpw+1]),
                                    fmaxf(A[(2*dph+1)*4 + 2*dpw], A[(2*dph+1)*4 + 2*dpw+1]));
                    m = fmaxf(m + bj, 0.f);
                    sm[S_P2 + oc * 16 + (2*qph + dph) * 4 + (2*qpw + dpw)] = q8(m);
                }
        }
    }
    __syncthreads();

    // ---- stage 3: fc1 partials (k-split x2) -------------------------------
    if (tid < 100) {
        const int l = tid % 50;
        const int s = tid / 50;
        const float* wT = g_qf1wT + l;
        const float* p2 = sm + S_P2;
        float acc = 0.f;
        const int k0 = 160 * s;
        #pragma unroll 4
        for (int k = k0; k < k0 + 160; k++)
            acc = fmaf(__ldg(wT + k * 52), p2[k], acc);
        sm[S_PART + s * 52 + l] = acc;
    }
    __syncthreads();

    // ---- stage 4: fc1 reduce + clip/relu/q8 -------------------------------
    if (tid < 50) {
        float acc = sm[S_PART + tid] + sm[S_PART + 52 + tid];
        float h = clipf(acc + __ldg(&g_qf1b[tid]));
        h = fmaxf(h, 0.f);
        sm[S_H1 + tid] = q8(h);
    }
    __syncthreads();

    // ---- stage 5: fc2 + clip ---------------------------------------------
    if (tid < 10) {
        const float* w = g_qf2w + tid * 50;
        float acc = 0.f;
        #pragma unroll
        for (int k = 0; k < 50; k++) acc = fmaf(__ldg(w + k), sm[S_H1 + k], acc);
        sm[S_Z + tid] = clipf(acc + __ldg(&g_qf2b[tid]));
    }
    __syncthreads();

    // ---- stage 6: log_softmax --------------------------------------------
    if (tid < 10) {
        const float* z = sm + S_Z;
        float m = -1e30f;
        #pragma unroll
        for (int k = 0; k < 10; k++) m = fmaxf(m, z[k]);
        float s = 0.f;
        #pragma unroll
        for (int k = 0; k < 10; k++) s += expf(z[k] - m);
        out[blk * 10 + tid] = z[tid] - m - logf(s);
    }
}

// ---------------------------------------------------------------------------
extern "C" void kernel_launch(void* const* d_in, const int* in_sizes, int n_in,
                              void* d_out, int out_size)
{
    const float* x   = (const float*)d_in[0];
    const float* c1w = (const float*)d_in[1];
    const float* c1b = (const float*)d_in[2];
    const float* c2w = (const float*)d_in[3];
    const float* c2b = (const float*)d_in[4];
    const float* f1w = (const float*)d_in[5];
    const float* f1b = (const float*)d_in[6];
    const float* f2w = (const float*)d_in[7];
    const float* f2b = (const float*)d_in[8];
    float* out = (float*)d_out;

    k_quant_weights<<<(23110 + 255) / 256, 256>>>(c1w, c1b, c2w, c2b, f1w, f1b, f2w, f2b);
    k_fused<<<B, NTHR>>>(x, out);
}

// round 12
// speedup vs baseline: 1.7506x; 1.3627x over previous
#include <cuda_runtime.h>
#include <cuda_bf16.h>
#include <math.h>

// Fused quantized LeNet, round 12: exact R5 chassis (best, 36.9us) with ONE
// change: conv2 weights staged per-block into smem as bf16 (q8 weights are
// exactly representable in bf16), removing 70 LDG.128/thread of 4-line
// weight wavefronts from conv2's inner loop. 7 blocks/SM single wave kept.
// Conv per-product clip never fires (|w*x| <= ~13 << 255): convs pure FMA.

#define B        1024
#define NTHR     160

__device__ __forceinline__ float q8(float x) {
    return rintf(x * 256.0f) * 0.00390625f;   // round-half-even, scale 2^-8
}
__device__ __forceinline__ float clipf(float x) {
    return fminf(fmaxf(x, -256.0f), 255.0f);
}

// ---- quantized weight scratch ---------------------------------------------
__device__ __align__(16) float g_qc1wp[280];     // 10 x 28 (25 taps + pad), q8
__device__ float g_qc1b[10];
__device__ __align__(16) __nv_bfloat16 g_qc2wh[6400]; // 20x10x32 taps, q8->bf16 (exact)
__device__ float g_qc2b[20];
__device__ __align__(16) float g_qf1wT[16640];   // 320 x 52 transposed, clip(q8)
__device__ float g_qf1b[50];
__device__ __align__(16) float g_qf2w[500];      // 10 x 50, clip(q8)
__device__ float g_qf2b[10];

// ---------------------------------------------------------------------------
__global__ void k_quant_weights(const float* __restrict__ c1w, const float* __restrict__ c1b,
                                const float* __restrict__ c2w, const float* __restrict__ c2b,
                                const float* __restrict__ f1w, const float* __restrict__ f1b,
                                const float* __restrict__ f2w, const float* __restrict__ f2b)
{
    int i = blockIdx.x * blockDim.x + threadIdx.x;
    if (i < 280) {
        int j = i / 28, t = i % 28;
        g_qc1wp[i] = (t < 25) ? q8(c1w[j * 25 + t]) : 0.f;
    } else if (i < 290) {
        g_qc1b[i - 280] = q8(c1b[i - 280]);
    } else if (i < 6690) {                         // conv2 weights, bf16 padded-32
        int r = i - 290;
        int jc = r / 32, t = r % 32;
        float v = (t < 25) ? q8(c2w[jc * 25 + t]) : 0.f;
        g_qc2wh[r] = __float2bfloat16(v);          // exact: q8 vals fit bf16
    } else if (i < 6710) {
        g_qc2b[i - 6690] = q8(c2b[i - 6690]);
    } else if (i < 23350) {
        int r = i - 6710;
        int k = r / 52, l = r % 52;
        g_qf1wT[r] = (l < 50) ? clipf(q8(f1w[l * 320 + k])) : 0.f;
    } else if (i < 23400) {
        g_qf1b[i - 23350] = clipf(q8(f1b[i - 23350]));
    } else if (i < 23900) {
        g_qf2w[i - 23400] = clipf(q8(f2w[i - 23400]));
    } else if (i < 23910) {
        g_qf2b[i - 23900] = clipf(q8(f2b[i - 23900]));
    }
}

// ---- smem layout (floats) --------------------------------------------------
#define S_XQ    0        // 784           (aliased by fc scratch after conv1)
#define S_P1    784      // 10 ch x 12 rows x 20 = 2400 (rows padded to 20)
#define S_P2    3184     // 320
#define S_C2WH  3504     // 6400 bf16 = 3200 float-slots (16B aligned: 3504*4%16==0)
#define S_TOT   6704     // 26816 bytes -> 7 blocks/SM (188KB), single wave
// fc scratch aliases S_XQ:
#define S_PART 0         // [2 slices][52]
#define S_H1   104       // [52]
#define S_Z    160       // [12]

// Load 25 padded taps (7 float4) from gmem into registers (conv1).
__device__ __forceinline__ void load_w25_f32(const float* gw, float* wr)
{
    const float4* w4 = (const float4*)gw;
    float wf[28];
    #pragma unroll
    for (int q = 0; q < 7; q++) {
        float4 t = __ldg(w4 + q);
        wf[q*4+0]=t.x; wf[q*4+1]=t.y; wf[q*4+2]=t.z; wf[q*4+3]=t.w;
    }
    #pragma unroll
    for (int q = 0; q < 25; q++) wr[q] = wf[q];
}

// Load 25 taps from smem bf16 (channel stride 32 bf16 = 64B, 16B aligned).
__device__ __forceinline__ void load_w25_bf16(const __nv_bfloat162* wh, float* wr)
{
    #pragma unroll
    for (int q = 0; q < 12; q++) {
        float2 f = __bfloat1622float2(wh[q]);
        wr[2*q]   = f.x;
        wr[2*q+1] = f.y;
    }
    wr[24] = __bfloat162float(wh[12].x);
}

// ---------------------------------------------------------------------------
__global__ __launch_bounds__(NTHR) void k_fused(const float* __restrict__ x,
                                                float* __restrict__ out)
{
    __shared__ __align__(16) float sm[S_TOT];
    const int tid = threadIdx.x;
    const int blk = blockIdx.x;

    // ---- stage 0: quantized input + conv2 bf16 weights to smem ------------
    {
        const float* xin = x + (size_t)blk * 784;
        for (int i = tid; i < 784; i += NTHR) sm[S_XQ + i] = q8(xin[i]);
        // copy 6400 bf16 = 12800B = 800 x 16B
        const uint4* src = (const uint4*)g_qc2wh;
        uint4* dst = (uint4*)(sm + S_C2WH);
        #pragma unroll
        for (int i = tid; i < 800; i += NTHR) dst[i] = __ldg(src + i);
    }
    __syncthreads();

    // ---- stage 1: conv1 + pool + relu -> s_p1 (R5-proven mapping) ---------
    // thread = (j in 10, tt in 16); adjacent-pw pairs, c0 4-aligned.
    {
        const int j  = tid / 16;
        const int tt = tid % 16;
        float wr[25];
        load_w25_f32(g_qc1wp + j * 28, wr);
        const float bj = __ldg(&g_qc1b[j]);
        const float* xb = sm + S_XQ;
        float* outp = sm + S_P1 + j * 240;

        #pragma unroll
        for (int qq = 0; qq < 5; qq++) {
            const int q = tt + 16 * qq;          // 0..79, guard <72
            if (q < 72) {
                const int ph = q / 6, pwp = q % 6;
                const int r0 = 2 * ph, cb = 4 * pwp;

                float a[8];
                #pragma unroll
                for (int z = 0; z < 8; z++) a[z] = 0.f;

                #pragma unroll
                for (int r = 0; r < 6; r++) {
                    const float* rp = xb + (r0 + r) * 28 + cb;
                    float4 A = *(const float4*)rp;
                    float4 C = *(const float4*)(rp + 4);
                    float row[8] = {A.x, A.y, A.z, A.w, C.x, C.y, C.z, C.w};
                    if (r < 5) {
                        #pragma unroll
                        for (int v = 0; v < 5; v++) {
                            const float wv = wr[r * 5 + v];
                            a[0] = fmaf(wv, row[v],     a[0]);
                            a[1] = fmaf(wv, row[v + 1], a[1]);
                            a[4] = fmaf(wv, row[v + 2], a[4]);
                            a[5] = fmaf(wv, row[v + 3], a[5]);
                        }
                    }
                    if (r >= 1) {
                        #pragma unroll
                        for (int v = 0; v < 5; v++) {
                            const float wv = wr[(r - 1) * 5 + v];
                            a[2] = fmaf(wv, row[v],     a[2]);
                            a[3] = fmaf(wv, row[v + 1], a[3]);
                            a[6] = fmaf(wv, row[v + 2], a[6]);
                            a[7] = fmaf(wv, row[v + 3], a[7]);
                        }
                    }
                }
                float m0 = fmaxf(fmaxf(a[0], a[1]), fmaxf(a[2], a[3])) + bj;
                float m1 = fmaxf(fmaxf(a[4], a[5]), fmaxf(a[6], a[7])) + bj;
                outp[ph * 20 + 2 * pwp]     = fmaxf(m0, 0.f);
                outp[ph * 20 + 2 * pwp + 1] = fmaxf(m1, 0.f);
            }
        }
    }
    __syncthreads();

    // ---- stage 2: conv2 + pool + relu + q8 -> s_p2 (R5 mapping) -----------
    // thread = (oc in 20, ph in 4, pwh in 2); weights from smem bf16.
    {
        const int oc  = tid >> 3;
        const int pp  = tid & 7;
        const int ph  = pp >> 1;
        const int pwh = pp & 1;
        const int r0  = 2 * ph;
        const int cbase = 4 * pwh;

        float a[8];
        #pragma unroll
        for (int z = 0; z < 8; z++) a[z] = 0.f;

        const __nv_bfloat162* whbase =
            (const __nv_bfloat162*)(sm + S_C2WH) + oc * 160;  // 10ch x 16 bf162

        #pragma unroll 1
        for (int c = 0; c < 10; c++) {
            float wr[25];
            load_w25_bf16(whbase + c * 16, wr);
            const float* xc = sm + S_P1 + c * 240 + cbase;
            #pragma unroll
            for (int r = 0; r < 6; r++) {
                const float* rp = xc + (r0 + r) * 20;
                float4 A = *(const float4*)rp;
                float4 C = *(const float4*)(rp + 4);
                float row[8] = {A.x, A.y, A.z, A.w, C.x, C.y, C.z, C.w};
                if (r < 5) {
                    #pragma unroll
                    for (int v = 0; v < 5; v++) {
                        const float wv = wr[r * 5 + v];
                        a[0] = fmaf(wv, row[v],     a[0]);
                        a[1] = fmaf(wv, row[v + 1], a[1]);
                        a[4] = fmaf(wv, row[v + 2], a[4]);
                        a[5] = fmaf(wv, row[v + 3], a[5]);
                    }
                }
                if (r >= 1) {
                    #pragma unroll
                    for (int v = 0; v < 5; v++) {
                        const float wv = wr[(r - 1) * 5 + v];
                        a[2] = fmaf(wv, row[v],     a[2]);
                        a[3] = fmaf(wv, row[v + 1], a[3]);
                        a[6] = fmaf(wv, row[v + 2], a[6]);
                        a[7] = fmaf(wv, row[v + 3], a[7]);
                    }
                }
            }
        }
        const float bj = __ldg(&g_qc2b[oc]);
        float m0 = fmaxf(fmaxf(a[0], a[1]), fmaxf(a[2], a[3])) + bj;
        float m1 = fmaxf(fmaxf(a[4], a[5]), fmaxf(a[6], a[7])) + bj;
        sm[S_P2 + oc * 16 + ph * 4 + pwh * 2]     = q8(fmaxf(m0, 0.f));
        sm[S_P2 + oc * 16 + ph * 4 + pwh * 2 + 1] = q8(fmaxf(m1, 0.f));
    }
    __syncthreads();

    // ---- stage 3: fc1 partials (k-split x2) -------------------------------
    if (tid < 100) {
        const int l = tid % 50;
        const int s = tid / 50;
        const float* wT = g_qf1wT + l;
        const float* p2 = sm + S_P2;
        float acc = 0.f;
        const int k0 = 160 * s;
        #pragma unroll 4
        for (int k = k0; k < k0 + 160; k++)
            acc = fmaf(__ldg(wT + k * 52), p2[k], acc);
        sm[S_PART + s * 52 + l] = acc;
    }
    __syncthreads();

    // ---- stage 4: fc1 reduce + clip/relu/q8 -------------------------------
    if (tid < 50) {
        float acc = sm[S_PART + tid] + sm[S_PART + 52 + tid];
        float h = clipf(acc + __ldg(&g_qf1b[tid]));
        h = fmaxf(h, 0.f);
        sm[S_H1 + tid] = q8(h);
    }
    __syncthreads();

    // ---- stage 5: fc2 + clip ---------------------------------------------
    if (tid < 10) {
        const float* w = g_qf2w + tid * 50;
        float acc = 0.f;
        #pragma unroll
        for (int k = 0; k < 50; k++) acc = fmaf(__ldg(w + k), sm[S_H1 + k], acc);
        sm[S_Z + tid] = clipf(acc + __ldg(&g_qf2b[tid]));
    }
    __syncthreads();

    // ---- stage 6: log_softmax --------------------------------------------
    if (tid < 10) {
        const float* z = sm + S_Z;
        float m = -1e30f;
        #pragma unroll
        for (int k = 0; k < 10; k++) m = fmaxf(m, z[k]);
        float s = 0.f;
        #pragma unroll
        for (int k = 0; k < 10; k++) s += expf(z[k] - m);
        out[blk * 10 + tid] = z[tid] - m - logf(s);
    }
}

// ---------------------------------------------------------------------------
extern "C" void kernel_launch(void* const* d_in, const int* in_sizes, int n_in,
                              void* d_out, int out_size)
{
    const float* x   = (const float*)d_in[0];
    const float* c1w = (const float*)d_in[1];
    const float* c1b = (const float*)d_in[2];
    const float* c2w = (const float*)d_in[3];
    const float* c2b = (const float*)d_in[4];
    const float* f1w = (const float*)d_in[5];
    const float* f1b = (const float*)d_in[6];
    const float* f2w = (const float*)d_in[7];
    const float* f2b = (const float*)d_in[8];
    float* out = (float*)d_out;

    k_quant_weights<<<(23910 + 255) / 256, 256>>>(c1w, c1b, c2w, c2b, f1w, f1b, f2w, f2b);
    k_fused<<<B, NTHR>>>(x, out);
}